// round 14
// baseline (speedup 1.0000x reference)
#include <cuda_runtime.h>
#include <cuda_fp16.h>
#include <cstdint>
#include <math.h>

#define Bv 4
#define Tv 2048
#define Cv 1024
#define Hv 16
#define Dv 64
#define Mv (Bv*Tv)          // 8192 rows

// ---------------- scratch (device globals; no allocations allowed) ----------
__device__ __half g_q[Mv*Cv];
__device__ __half g_k[Mv*Cv];
__device__ __half g_vt[Bv*Hv*Dv*Tv];   // V transposed per (b,h): [d][t]
__device__ __half g_att[Mv*Cv];
__device__ __half g_xh[Mv*Cv];         // fp16 x
__device__ __half g_wh[4*Cv*Cv];       // fp16 wq,wk,wv,wo (contiguous)

__device__ __forceinline__ uint32_t smem_u32(const void* p) {
    uint32_t a;
    asm("{ .reg .u64 t; cvta.to.shared.u64 t, %1; cvt.u32.u64 %0, t; }"
        : "=r"(a) : "l"(p));
    return a;
}
__device__ __forceinline__ void cp16(uint32_t saddr, const void* gaddr) {
    asm volatile("cp.async.cg.shared.global [%0], [%1], 16;"
                 :: "r"(saddr), "l"(gaddr));
}
__device__ __forceinline__ void mma_f16(float* d, const uint32_t* a, const uint32_t* b) {
    asm volatile("mma.sync.aligned.m16n8k16.row.col.f32.f16.f16.f32 "
                 "{%0,%1,%2,%3}, {%4,%5,%6,%7}, {%8,%9}, {%0,%1,%2,%3};"
                 : "+f"(d[0]), "+f"(d[1]), "+f"(d[2]), "+f"(d[3])
                 : "r"(a[0]), "r"(a[1]), "r"(a[2]), "r"(a[3]), "r"(b[0]), "r"(b[1]));
}
#define LDM_X4(r0,r1,r2,r3, addr) \
    asm volatile("ldmatrix.sync.aligned.m8n8.x4.shared.b16 {%0,%1,%2,%3}, [%4];" \
                 : "=r"(r0),"=r"(r1),"=r"(r2),"=r"(r3) : "r"(addr))

// ---------------------------------------------------------------------------
// single-launch rounding to fp16: x (Mv*Cv) then wq|wk|wv|wo into g_xh/g_wh
// ---------------------------------------------------------------------------
__global__ void round_all(const float4* __restrict__ x,
                          const float4* __restrict__ w0, const float4* __restrict__ w1,
                          const float4* __restrict__ w2, const float4* __restrict__ w3,
                          __half2* __restrict__ xh, __half2* __restrict__ wh)
{
    const int nx = Mv * Cv / 4;
    const int per = Cv * Cv / 4;
    int i = blockIdx.x * blockDim.x + threadIdx.x;
    float4 v; __half2* dst;
    if (i < nx) {
        v = x[i]; dst = xh + 2 * i;
    } else {
        int j = i - nx;
        if (j >= 4 * per) return;
        const float4* src = (j < per) ? w0 : (j < 2*per) ? w1 : (j < 3*per) ? w2 : w3;
        v = src[j & (per - 1)];
        dst = wh + 2 * j;
    }
    dst[0] = __floats2half2_rn(v.x, v.y);
    dst[1] = __floats2half2_rn(v.z, v.w);
}

// ---------------------------------------------------------------------------
// fp16 mma.sync GEMM (m16n8k16):  C[M,N] = A[M,K] · B[N,K]^T
// CTA 256x128, 8 warps as 4x2, warp tile 64x64 (ratio 32 MMA / 8 ldmatrix.x4),
// BK=64 (128B fp16 rows), 3-stage cp.async pipeline, XOR-swizzled smem.
// smem = 3 * 49152 = 147456 B -> 1 CTA/SM.
// qkv mode: n-block 0-7 -> Q (scaled 0.125), 8-15 -> K, 16-23 -> V transposed.
// ---------------------------------------------------------------------------
#define GBK   64
#define ABUF_A 32768             // 256 rows * 128 B
#define ABUF_B 16384             // 128 rows * 128 B
#define STGB  (ABUF_A + ABUF_B)  // 49152
#define NITER (Cv/GBK)           // 16
#define SWA(base, r, u) ((base) + (r) * 128 + (((u) ^ ((r) & 7)) << 4))

__global__ __launch_bounds__(256, 1)
void gemm_h(const __half* __restrict__ A, const __half* __restrict__ B,
            void* __restrict__ C0v, void* __restrict__ C1v,
            void* __restrict__ C2v, int qkv)
{
    extern __shared__ __align__(128) char smem[];
    const uint32_t sb = smem_u32(smem);
    const int tid  = threadIdx.x;
    const int wid  = tid >> 5;
    const int lane = tid & 31;
    const int m0 = blockIdx.y * 256, n0 = blockIdx.x * 128;
    const int wm = (wid >> 1) * 64;      // 4 m-warps
    const int wn = (wid & 1) * 64;       // 2 n-warps
    const int kph = ((blockIdx.x ^ blockIdx.y) & 1) * (NITER / 2);

    float acc[4][8][4];
    #pragma unroll
    for (int i = 0; i < 4; i++)
        #pragma unroll
        for (int j = 0; j < 8; j++)
            #pragma unroll
            for (int k = 0; k < 4; k++) acc[i][j][k] = 0.f;

    // loaders: A 2048 16B-units (8/thr), B 1024 units (4/thr)
    const int lr = tid >> 3;             // base row (+32 per i)
    const int lu = tid & 7;
    const int lc = lu * 8;               // half col

    #pragma unroll
    for (int s = 0; s < 2; s++) {
        const int kc = ((s + kph) & (NITER - 1)) * GBK;
        const uint32_t sA = sb + s * STGB, sB2 = sA + ABUF_A;
        #pragma unroll
        for (int i = 0; i < 8; i++) {
            int r = lr + i * 32;
            cp16(SWA(sA, r, lu), A + (size_t)(m0 + r) * Cv + kc + lc);
        }
        #pragma unroll
        for (int i = 0; i < 4; i++) {
            int r = lr + i * 32;
            cp16(SWA(sB2, r, lu), B + (size_t)(n0 + r) * Cv + kc + lc);
        }
        asm volatile("cp.async.commit_group;");
    }

    for (int it = 0; it < NITER; ++it) {
        if (it < NITER - 1) asm volatile("cp.async.wait_group 1;");
        else                asm volatile("cp.async.wait_group 0;");
        __syncthreads();

        if (it + 2 < NITER) {
            const int kc = ((it + 2 + kph) & (NITER - 1)) * GBK;
            const uint32_t db = sb + ((it + 2) % 3) * STGB;
            const uint32_t dA = db, dB = db + ABUF_A;
            #pragma unroll
            for (int i = 0; i < 8; i++) {
                int r = lr + i * 32;
                cp16(SWA(dA, r, lu), A + (size_t)(m0 + r) * Cv + kc + lc);
            }
            #pragma unroll
            for (int i = 0; i < 4; i++) {
                int r = lr + i * 32;
                cp16(SWA(dB, r, lu), B + (size_t)(n0 + r) * Cv + kc + lc);
            }
            asm volatile("cp.async.commit_group;");
        }

        const uint32_t base = sb + (it % 3) * STGB;
        const uint32_t sA = base, sB = base + ABUF_A;

        #pragma unroll
        for (int ks = 0; ks < 4; ++ks) {          // 4 x k16
            const int u0 = ks * 2;
            uint32_t af[4][4], bf[8][2];
            #pragma unroll
            for (int mf = 0; mf < 4; ++mf) {
                int row = wm + mf * 16 + (lane & 15);
                int u = u0 + (lane >> 4);
                LDM_X4(af[mf][0], af[mf][1], af[mf][2], af[mf][3], SWA(sA, row, u));
            }
            #pragma unroll
            for (int np = 0; np < 4; ++np) {
                int row = wn + np * 16 + ((lane & 16) >> 1) + (lane & 7);
                int u = u0 + ((lane & 8) >> 3);
                uint32_t r0, r1, r2, r3;
                LDM_X4(r0, r1, r2, r3, SWA(sB, row, u));
                bf[np*2+0][0] = r0; bf[np*2+0][1] = r1;
                bf[np*2+1][0] = r2; bf[np*2+1][1] = r3;
            }
            #pragma unroll
            for (int mf = 0; mf < 4; ++mf)
                #pragma unroll
                for (int nf = 0; nf < 8; ++nf)
                    mma_f16(acc[mf][nf], af[mf], bf[nf]);
        }
    }

    const int rA = lane >> 2;
    const int cA = (lane & 3) * 2;

    if (qkv) {
        if (n0 >= 2048) {
            // V segment -> transposed halves into g_vt [(b*16+h)*64+d][t]
            __half* C2 = (__half*)C2v;
            #pragma unroll
            for (int mf = 0; mf < 4; ++mf)
                #pragma unroll
                for (int nf = 0; nf < 8; ++nf) {
                    int row = m0 + wm + mf * 16 + rA;          // token
                    int col = (n0 - 2048) + wn + nf * 8 + cA;  // V col
                    int b2 = row >> 11, t2 = row & 2047;
                    int h2 = col >> 6, d2 = col & 63;
                    __half* vb = C2 + ((size_t)((b2 * 16 + h2) * 64 + d2)) * Tv + t2;
                    vb[0]      = __float2half_rn(acc[mf][nf][0]);
                    vb[Tv]     = __float2half_rn(acc[mf][nf][1]);
                    vb[8]      = __float2half_rn(acc[mf][nf][2]);
                    vb[Tv + 8] = __float2half_rn(acc[mf][nf][3]);
                }
            return;
        }
        __half* C = (n0 >= 1024) ? (__half*)C1v : (__half*)C0v;
        const int nn = n0 & 1023;
        const float sc = (n0 < 1024) ? 0.125f : 1.0f;   // fold softmax scale into Q
        #pragma unroll
        for (int mf = 0; mf < 4; ++mf)
            #pragma unroll
            for (int nf = 0; nf < 8; ++nf) {
                int row = m0 + wm + mf * 16 + rA;
                int col = nn + wn + nf * 8 + cA;
                *(__half2*)(C + (size_t)row * Cv + col) =
                    __floats2half2_rn(acc[mf][nf][0] * sc, acc[mf][nf][1] * sc);
                *(__half2*)(C + (size_t)(row + 8) * Cv + col) =
                    __floats2half2_rn(acc[mf][nf][2] * sc, acc[mf][nf][3] * sc);
            }
        return;
    }

    float* C = (float*)C0v;
    #pragma unroll
    for (int mf = 0; mf < 4; ++mf)
        #pragma unroll
        for (int nf = 0; nf < 8; ++nf) {
            int row = m0 + wm + mf * 16 + rA;
            int col = n0 + wn + nf * 8 + cA;
            *(float2*)(C + (size_t)row * Cv + col) =
                make_float2(acc[mf][nf][0], acc[mf][nf][1]);
            *(float2*)(C + (size_t)(row + 8) * Cv + col) =
                make_float2(acc[mf][nf][2], acc[mf][nf][3]);
        }
}

// ---------------------------------------------------------------------------
// Causal flash attention, fp16 m16n8k16 — BM=256 (8 warps x 32 q-rows), BN=64.
// K and pre-transposed Vt double-buffered via cp.async; one barrier per tile.
// HPAD=72 halves (144B rows). smem = 110592 B.
// ---------------------------------------------------------------------------
#define HPAD  72
#define HROWB (HPAD*2)            // 144 B per row
#define KVTB  (64*HROWB)          // 9216 B per K/V tile
#define QOFFB 0
#define KOFFB (256*HROWB)         // 36864
#define TOFFB (KOFFB + 2*KVTB)    // 55296
#define POFFB (TOFFB + 2*KVTB)    // 73728
#define FSMEM (POFFB + 256*HROWB) // 110592 B
#define HADDR(base, r, u) ((base) + (r) * HROWB + (u) * 16)

__global__ __launch_bounds__(256)
void flash_mma(const __half* __restrict__ Qg, const __half* __restrict__ Kg,
               const __half* __restrict__ Vtg, __half* __restrict__ Og)
{
    extern __shared__ __align__(16) char fsm[];
    const uint32_t sb = smem_u32(fsm);
    const uint32_t sQ  = sb + QOFFB;
    const uint32_t sK0 = sb + KOFFB;
    const uint32_t sT0 = sb + TOFFB;
    const uint32_t sP  = sb + POFFB;
    __half* Ph = (__half*)(fsm + POFFB);

    const int tid = threadIdx.x;
    const int wid = tid >> 5, lane = tid & 31;
    const int g = lane >> 2, t = lane & 3;
    const int qt = (int)(gridDim.x - 1 - blockIdx.x);   // heavy CTAs first
    const int bh = blockIdx.y;
    const int b = bh >> 4, h = bh & 15;
    const int q0 = qt * 256;
    const int ktiles = 4 * qt + 4;
    const size_t base = (size_t)b * Tv * Cv + (size_t)h * Dv;
    const __half* vtb = Vtg + (size_t)bh * Dv * Tv;

    {
        const __half* qb = Qg + base + (size_t)q0 * Cv;
        const __half* kb = Kg + base;
        #pragma unroll
        for (int i = 0; i < 8; i++) {
            int id = tid + i * 256, r = id >> 3, u = id & 7;
            cp16(HADDR(sQ, r, u), qb + (size_t)r * Cv + u * 8);
        }
        #pragma unroll
        for (int i = 0; i < 2; i++) {
            int id = tid + i * 256, r = id >> 3, u = id & 7;
            cp16(HADDR(sK0, r, u), kb + (size_t)r * Cv + u * 8);
            cp16(HADDR(sT0, r, u), vtb + (size_t)r * Tv + u * 8);
        }
        asm volatile("cp.async.commit_group;");
    }

    float oacc[2][8][4];
    #pragma unroll
    for (int mf = 0; mf < 2; mf++)
        #pragma unroll
        for (int nf = 0; nf < 8; nf++)
            #pragma unroll
            for (int k = 0; k < 4; k++) oacc[mf][nf][k] = 0.f;
    float mrow[2][2], lrow[2][2];
    #pragma unroll
    for (int mf = 0; mf < 2; mf++) {
        mrow[mf][0] = -1e30f; mrow[mf][1] = -1e30f;
        lrow[mf][0] = 0.f;    lrow[mf][1] = 0.f;
    }
    uint32_t qf[2][4][4];

    for (int kt = 0; kt < ktiles; ++kt) {
        const int cur = kt & 1;
        asm volatile("cp.async.wait_group 0;");
        __syncthreads();
        if (kt + 1 < ktiles) {
            int nb = cur ^ 1;
            const __half* kb = Kg + base + (size_t)((kt + 1) * 64) * Cv;
            const __half* vb = vtb + (kt + 1) * 64;
            #pragma unroll
            for (int i = 0; i < 2; i++) {
                int id = tid + i * 256, r = id >> 3, u = id & 7;
                cp16(HADDR(sK0 + nb * KVTB, r, u), kb + (size_t)r * Cv + u * 8);
                cp16(HADDR(sT0 + nb * KVTB, r, u), vb + (size_t)r * Tv + u * 8);
            }
            asm volatile("cp.async.commit_group;");
        }
        if (kt == 0) {
            #pragma unroll
            for (int mf = 0; mf < 2; mf++)
                #pragma unroll
                for (int ks = 0; ks < 4; ks++) {
                    int row = wid * 32 + mf * 16 + (lane & 15);
                    int u = ks * 2 + (lane >> 4);
                    LDM_X4(qf[mf][ks][0], qf[mf][ks][1], qf[mf][ks][2], qf[mf][ks][3],
                           HADDR(sQ, row, u));
                }
        }
        const uint32_t sKb = sK0 + cur * KVTB;
        const uint32_t sTb = sT0 + cur * KVTB;

        float sacc[2][8][4];
        #pragma unroll
        for (int mf = 0; mf < 2; mf++)
            #pragma unroll
            for (int nf = 0; nf < 8; nf++)
                #pragma unroll
                for (int k = 0; k < 4; k++) sacc[mf][nf][k] = 0.f;

        #pragma unroll
        for (int ks = 0; ks < 4; ks++) {
            const int u0 = ks * 2;
            uint32_t bf[8][2];
            #pragma unroll
            for (int np = 0; np < 4; np++) {
                int row = np * 16 + ((lane & 16) >> 1) + (lane & 7);
                int u = u0 + ((lane & 8) >> 3);
                uint32_t r0, r1, r2, r3;
                LDM_X4(r0, r1, r2, r3, HADDR(sKb, row, u));
                bf[np*2+0][0] = r0; bf[np*2+0][1] = r1;
                bf[np*2+1][0] = r2; bf[np*2+1][1] = r3;
            }
            #pragma unroll
            for (int mf = 0; mf < 2; mf++)
                #pragma unroll
                for (int nf = 0; nf < 8; nf++)
                    mma_f16(sacc[mf][nf], qf[mf][ks], bf[nf]);
        }

        if (kt >= 4 * qt) {
            const int k0 = kt * 64;
            #pragma unroll
            for (int mf = 0; mf < 2; mf++) {
                int r0g = q0 + wid * 32 + mf * 16 + g, r1g = r0g + 8;
                #pragma unroll
                for (int nf = 0; nf < 8; nf++) {
                    int c0 = k0 + nf * 8 + 2 * t;
                    if (c0     > r0g) sacc[mf][nf][0] = -1e30f;
                    if (c0 + 1 > r0g) sacc[mf][nf][1] = -1e30f;
                    if (c0     > r1g) sacc[mf][nf][2] = -1e30f;
                    if (c0 + 1 > r1g) sacc[mf][nf][3] = -1e30f;
                }
            }
        }

        #pragma unroll
        for (int mf = 0; mf < 2; mf++) {
            float mx0 = -1e30f, mx1 = -1e30f;
            #pragma unroll
            for (int nf = 0; nf < 8; nf++) {
                mx0 = fmaxf(mx0, fmaxf(sacc[mf][nf][0], sacc[mf][nf][1]));
                mx1 = fmaxf(mx1, fmaxf(sacc[mf][nf][2], sacc[mf][nf][3]));
            }
            #pragma unroll
            for (int off = 1; off < 4; off <<= 1) {
                mx0 = fmaxf(mx0, __shfl_xor_sync(0xffffffffu, mx0, off));
                mx1 = fmaxf(mx1, __shfl_xor_sync(0xffffffffu, mx1, off));
            }
            float nm0 = fmaxf(mrow[mf][0], mx0), nm1 = fmaxf(mrow[mf][1], mx1);
            float al0 = __expf(mrow[mf][0] - nm0), al1 = __expf(mrow[mf][1] - nm1);
            float rs0 = 0.f, rs1 = 0.f;
            #pragma unroll
            for (int nf = 0; nf < 8; nf++) {
                float p0 = __half2float(__float2half_rn(__expf(sacc[mf][nf][0] - nm0)));
                float p1 = __half2float(__float2half_rn(__expf(sacc[mf][nf][1] - nm0)));
                float p2 = __half2float(__float2half_rn(__expf(sacc[mf][nf][2] - nm1)));
                float p3 = __half2float(__float2half_rn(__expf(sacc[mf][nf][3] - nm1)));
                sacc[mf][nf][0] = p0; sacc[mf][nf][1] = p1;
                sacc[mf][nf][2] = p2; sacc[mf][nf][3] = p3;
                rs0 += p0 + p1; rs1 += p2 + p3;
            }
            #pragma unroll
            for (int off = 1; off < 4; off <<= 1) {
                rs0 += __shfl_xor_sync(0xffffffffu, rs0, off);
                rs1 += __shfl_xor_sync(0xffffffffu, rs1, off);
            }
            lrow[mf][0] = lrow[mf][0] * al0 + rs0; mrow[mf][0] = nm0;
            lrow[mf][1] = lrow[mf][1] * al1 + rs1; mrow[mf][1] = nm1;
            #pragma unroll
            for (int nf = 0; nf < 8; nf++) {
                oacc[mf][nf][0] *= al0; oacc[mf][nf][1] *= al0;
                oacc[mf][nf][2] *= al1; oacc[mf][nf][3] *= al1;
            }
        }

        __syncwarp();
        #pragma unroll
        for (int mf = 0; mf < 2; mf++) {
            int pr0 = wid * 32 + mf * 16 + g, pr1 = pr0 + 8;
            #pragma unroll
            for (int nf = 0; nf < 8; nf++) {
                *(__half2*)&Ph[pr0 * HPAD + nf * 8 + 2 * t] =
                    __floats2half2_rn(sacc[mf][nf][0], sacc[mf][nf][1]);
                *(__half2*)&Ph[pr1 * HPAD + nf * 8 + 2 * t] =
                    __floats2half2_rn(sacc[mf][nf][2], sacc[mf][nf][3]);
            }
        }
        __syncwarp();

        #pragma unroll
        for (int ks = 0; ks < 4; ks++) {
            const int u0 = ks * 2;
            uint32_t af[2][4];
            #pragma unroll
            for (int mf = 0; mf < 2; mf++) {
                int row = wid * 32 + mf * 16 + (lane & 15);
                int u = u0 + (lane >> 4);
                LDM_X4(af[mf][0], af[mf][1], af[mf][2], af[mf][3], HADDR(sP, row, u));
            }
            uint32_t bf[8][2];
            #pragma unroll
            for (int np = 0; np < 4; np++) {
                int brow = np * 16 + ((lane & 16) >> 1) + (lane & 7);
                int u = u0 + ((lane & 8) >> 3);
                uint32_t r0, r1, r2, r3;
                LDM_X4(r0, r1, r2, r3, HADDR(sTb, brow, u));
                bf[np*2+0][0] = r0; bf[np*2+0][1] = r1;
                bf[np*2+1][0] = r2; bf[np*2+1][1] = r3;
            }
            #pragma unroll
            for (int mf = 0; mf < 2; mf++)
                #pragma unroll
                for (int nf = 0; nf < 8; nf++)
                    mma_f16(oacc[mf][nf], af[mf], bf[nf]);
        }
    }

    #pragma unroll
    for (int mf = 0; mf < 2; mf++) {
        float inv0 = 1.f / lrow[mf][0], inv1 = 1.f / lrow[mf][1];
        int r0g = q0 + wid * 32 + mf * 16 + g, r1g = r0g + 8;
        #pragma unroll
        for (int nf = 0; nf < 8; nf++) {
            int c = nf * 8 + 2 * t;
            *(__half2*)(Og + base + (size_t)r0g * Cv + c) =
                __floats2half2_rn(oacc[mf][nf][0] * inv0, oacc[mf][nf][1] * inv0);
            *(__half2*)(Og + base + (size_t)r1g * Cv + c) =
                __floats2half2_rn(oacc[mf][nf][2] * inv1, oacc[mf][nf][3] * inv1);
        }
    }
}

// ---------------------------------------------------------------------------
extern "C" void kernel_launch(void* const* d_in, const int* in_sizes, int n_in,
                              void* d_out, int out_size)
{
    const float* x  = (const float*)d_in[0];
    const float* wq = (const float*)d_in[1];
    const float* wk = (const float*)d_in[2];
    const float* wv = (const float*)d_in[3];
    const float* wo = (const float*)d_in[4];
    float* out = (float*)d_out;

    __half *qp, *kp, *vtp, *ap, *xh, *wh;
    cudaGetSymbolAddress((void**)&qp, g_q);
    cudaGetSymbolAddress((void**)&kp, g_k);
    cudaGetSymbolAddress((void**)&vtp, g_vt);
    cudaGetSymbolAddress((void**)&ap, g_att);
    cudaGetSymbolAddress((void**)&xh, g_xh);
    cudaGetSymbolAddress((void**)&wh, g_wh);

    const int ntot = (Mv * Cv + 4 * Cv * Cv) / 4;
    round_all<<<(ntot + 255) / 256, 256>>>((const float4*)x,
                                           (const float4*)wq, (const float4*)wk,
                                           (const float4*)wv, (const float4*)wo,
                                           (__half2*)xh, (__half2*)wh);

    const int gsmem = 3 * STGB;   // 147456
    cudaFuncSetAttribute(gemm_h, cudaFuncAttributeMaxDynamicSharedMemorySize, gsmem);

    // fused QKV: Q pre-scaled 0.125; V written transposed into g_vt
    gemm_h<<<dim3(24, Mv/256), 256, gsmem>>>(xh, wh, qp, kp, vtp, 1);

    cudaFuncSetAttribute(flash_mma, cudaFuncAttributeMaxDynamicSharedMemorySize, FSMEM);
    flash_mma<<<dim3(Tv/256, Bv*Hv), 256, FSMEM>>>(qp, kp, vtp, ap);

    gemm_h<<<dim3(8, Mv/256), 256, gsmem>>>(ap, wh + 3*(size_t)Cv*Cv, out,
                                            nullptr, nullptr, 0);
}

// round 15
// speedup vs baseline: 1.0480x; 1.0480x over previous
#include <cuda_runtime.h>
#include <cuda_fp16.h>
#include <cstdint>
#include <math.h>

#define Bv 4
#define Tv 2048
#define Cv 1024
#define Hv 16
#define Dv 64
#define Mv (Bv*Tv)          // 8192 rows

// ---------------- scratch (device globals; no allocations allowed) ----------
__device__ __half g_q[Mv*Cv];
__device__ __half g_k[Mv*Cv];
__device__ __half g_vt[Bv*Hv*Dv*Tv];   // V transposed per (b,h): [d][t]
__device__ __half g_att[Mv*Cv];
__device__ __half g_xh[Mv*Cv];         // fp16 x
__device__ __half g_wh[4*Cv*Cv];       // fp16 wq,wk,wv,wo (contiguous)

__device__ __forceinline__ uint32_t smem_u32(const void* p) {
    uint32_t a;
    asm("{ .reg .u64 t; cvta.to.shared.u64 t, %1; cvt.u32.u64 %0, t; }"
        : "=r"(a) : "l"(p));
    return a;
}
__device__ __forceinline__ void cp16(uint32_t saddr, const void* gaddr) {
    asm volatile("cp.async.cg.shared.global [%0], [%1], 16;"
                 :: "r"(saddr), "l"(gaddr));
}
__device__ __forceinline__ void mma_f16(float* d, const uint32_t* a, const uint32_t* b) {
    asm volatile("mma.sync.aligned.m16n8k16.row.col.f32.f16.f16.f32 "
                 "{%0,%1,%2,%3}, {%4,%5,%6,%7}, {%8,%9}, {%0,%1,%2,%3};"
                 : "+f"(d[0]), "+f"(d[1]), "+f"(d[2]), "+f"(d[3])
                 : "r"(a[0]), "r"(a[1]), "r"(a[2]), "r"(a[3]), "r"(b[0]), "r"(b[1]));
}
#define LDM_X4(r0,r1,r2,r3, addr) \
    asm volatile("ldmatrix.sync.aligned.m8n8.x4.shared.b16 {%0,%1,%2,%3}, [%4];" \
                 : "=r"(r0),"=r"(r1),"=r"(r2),"=r"(r3) : "r"(addr))

// ---------------------------------------------------------------------------
// single-launch rounding to fp16: x (Mv*Cv) then wq|wk|wv|wo into g_xh/g_wh
// ---------------------------------------------------------------------------
__global__ void round_all(const float4* __restrict__ x,
                          const float4* __restrict__ w0, const float4* __restrict__ w1,
                          const float4* __restrict__ w2, const float4* __restrict__ w3,
                          __half2* __restrict__ xh, __half2* __restrict__ wh)
{
    const int nx = Mv * Cv / 4;
    const int per = Cv * Cv / 4;
    int i = blockIdx.x * blockDim.x + threadIdx.x;
    float4 v; __half2* dst;
    if (i < nx) {
        v = x[i]; dst = xh + 2 * i;
    } else {
        int j = i - nx;
        if (j >= 4 * per) return;
        const float4* src = (j < per) ? w0 : (j < 2*per) ? w1 : (j < 3*per) ? w2 : w3;
        v = src[j & (per - 1)];
        dst = wh + 2 * j;
    }
    dst[0] = __floats2half2_rn(v.x, v.y);
    dst[1] = __floats2half2_rn(v.z, v.w);
}

// ---------------------------------------------------------------------------
// fp16 mma.sync GEMM (m16n8k16):  C[M,N] = A[M,K] · B[N,K]^T    [R13 config]
// CTA 128x128, BK=64 (128B fp16 rows), 256 thr, 3-stage cp.async pipeline,
// XOR-swizzled smem (98304 B) -> 2 CTAs/SM. 16 K-iterations.
// qkv mode: n-block 0-7 -> Q (scaled 0.125), 8-15 -> K, 16-23 -> V transposed.
// ---------------------------------------------------------------------------
#define GBK   64
#define ABUF  16384              // 128 rows * 128 B
#define STGB  (2*ABUF)
#define NITER (Cv/GBK)           // 16
#define SWA(base, r, u) ((base) + (r) * 128 + (((u) ^ ((r) & 7)) << 4))

__global__ __launch_bounds__(256, 2)
void gemm_h(const __half* __restrict__ A, const __half* __restrict__ B,
            void* __restrict__ C0v, void* __restrict__ C1v,
            void* __restrict__ C2v, int qkv)
{
    extern __shared__ __align__(128) char smem[];
    const uint32_t sb = smem_u32(smem);
    const int tid  = threadIdx.x;
    const int wid  = tid >> 5;
    const int lane = tid & 31;
    const int m0 = blockIdx.y * 128, n0 = blockIdx.x * 128;
    const int wm = (wid >> 2) * 64;
    const int wn = (wid & 3) * 32;
    const int lr = tid >> 3;
    const int lu = tid & 7;
    const int lc = lu * 8;
    const int kph = ((blockIdx.x ^ blockIdx.y) & 1) * (NITER / 2);

    float acc[4][4][4];
    #pragma unroll
    for (int i = 0; i < 4; i++)
        #pragma unroll
        for (int j = 0; j < 4; j++)
            #pragma unroll
            for (int k = 0; k < 4; k++) acc[i][j][k] = 0.f;

    #pragma unroll
    for (int s = 0; s < 2; s++) {
        const int kc = ((s + kph) & (NITER - 1)) * GBK;
        const uint32_t sA = sb + s * STGB, sB2 = sA + ABUF;
        #pragma unroll
        for (int i = 0; i < 4; i++) {
            int r = lr + i * 32;
            cp16(SWA(sA,  r, lu), A + (size_t)(m0 + r) * Cv + kc + lc);
            cp16(SWA(sB2, r, lu), B + (size_t)(n0 + r) * Cv + kc + lc);
        }
        asm volatile("cp.async.commit_group;");
    }

    for (int it = 0; it < NITER; ++it) {
        if (it < NITER - 1) asm volatile("cp.async.wait_group 1;");
        else                asm volatile("cp.async.wait_group 0;");
        __syncthreads();

        if (it + 2 < NITER) {
            const int kc = ((it + 2 + kph) & (NITER - 1)) * GBK;
            const uint32_t db = sb + ((it + 2) % 3) * STGB;
            const uint32_t dA = db, dB = db + ABUF;
            #pragma unroll
            for (int i = 0; i < 4; i++) {
                int r = lr + i * 32;
                cp16(SWA(dA, r, lu), A + (size_t)(m0 + r) * Cv + kc + lc);
                cp16(SWA(dB, r, lu), B + (size_t)(n0 + r) * Cv + kc + lc);
            }
            asm volatile("cp.async.commit_group;");
        }

        const uint32_t base = sb + (it % 3) * STGB;
        const uint32_t sA = base, sB = base + ABUF;

        #pragma unroll
        for (int ks = 0; ks < 4; ++ks) {
            const int u0 = ks * 2;
            uint32_t af[4][4], bf[4][2];
            #pragma unroll
            for (int mf = 0; mf < 4; ++mf) {
                int row = wm + mf * 16 + (lane & 15);
                int u = u0 + (lane >> 4);
                LDM_X4(af[mf][0], af[mf][1], af[mf][2], af[mf][3], SWA(sA, row, u));
            }
            #pragma unroll
            for (int np = 0; np < 2; ++np) {
                int row = wn + np * 16 + ((lane & 16) >> 1) + (lane & 7);
                int u = u0 + ((lane & 8) >> 3);
                uint32_t r0, r1, r2, r3;
                LDM_X4(r0, r1, r2, r3, SWA(sB, row, u));
                bf[np*2+0][0] = r0; bf[np*2+0][1] = r1;
                bf[np*2+1][0] = r2; bf[np*2+1][1] = r3;
            }
            #pragma unroll
            for (int mf = 0; mf < 4; ++mf)
                #pragma unroll
                for (int nf = 0; nf < 4; ++nf)
                    mma_f16(acc[mf][nf], af[mf], bf[nf]);
        }
    }

    const int rA = lane >> 2;
    const int cA = (lane & 3) * 2;

    if (qkv) {
        if (n0 >= 2048) {
            __half* C2 = (__half*)C2v;
            #pragma unroll
            for (int mf = 0; mf < 4; ++mf)
                #pragma unroll
                for (int nf = 0; nf < 4; ++nf) {
                    int row = m0 + wm + mf * 16 + rA;
                    int col = (n0 - 2048) + wn + nf * 8 + cA;
                    int b2 = row >> 11, t2 = row & 2047;
                    int h2 = col >> 6, d2 = col & 63;
                    __half* vb = C2 + ((size_t)((b2 * 16 + h2) * 64 + d2)) * Tv + t2;
                    vb[0]      = __float2half_rn(acc[mf][nf][0]);
                    vb[Tv]     = __float2half_rn(acc[mf][nf][1]);
                    vb[8]      = __float2half_rn(acc[mf][nf][2]);
                    vb[Tv + 8] = __float2half_rn(acc[mf][nf][3]);
                }
            return;
        }
        __half* C = (n0 >= 1024) ? (__half*)C1v : (__half*)C0v;
        const int nn = n0 & 1023;
        const float sc = (n0 < 1024) ? 0.125f : 1.0f;
        #pragma unroll
        for (int mf = 0; mf < 4; ++mf)
            #pragma unroll
            for (int nf = 0; nf < 4; ++nf) {
                int row = m0 + wm + mf * 16 + rA;
                int col = nn + wn + nf * 8 + cA;
                *(__half2*)(C + (size_t)row * Cv + col) =
                    __floats2half2_rn(acc[mf][nf][0] * sc, acc[mf][nf][1] * sc);
                *(__half2*)(C + (size_t)(row + 8) * Cv + col) =
                    __floats2half2_rn(acc[mf][nf][2] * sc, acc[mf][nf][3] * sc);
            }
        return;
    }

    float* C = (float*)C0v;
    #pragma unroll
    for (int mf = 0; mf < 4; ++mf)
        #pragma unroll
        for (int nf = 0; nf < 4; ++nf) {
            int row = m0 + wm + mf * 16 + rA;
            int col = n0 + wn + nf * 8 + cA;
            *(float2*)(C + (size_t)row * Cv + col) =
                make_float2(acc[mf][nf][0], acc[mf][nf][1]);
            *(float2*)(C + (size_t)(row + 8) * Cv + col) =
                make_float2(acc[mf][nf][2], acc[mf][nf][3]);
        }
}

// ---------------------------------------------------------------------------
// Causal flash attention, fp16 m16n8k16 — BM=256 (8 warps x 32 q-rows), BN=64.
// K and Vt in a 3-deep cp.async ring (prefetch depth 2); one barrier per tile.
// HPAD=72 halves (144B rows). smem = 129024 B.
// ---------------------------------------------------------------------------
#define HPAD  72
#define HROWB (HPAD*2)            // 144 B per row
#define KVTB  (64*HROWB)          // 9216 B per K/V tile
#define QOFFB 0
#define KOFFB (256*HROWB)         // 36864
#define TOFFB (KOFFB + 3*KVTB)    // 64512
#define POFFB (TOFFB + 3*KVTB)    // 92160
#define FSMEM (POFFB + 256*HROWB) // 129024 B
#define HADDR(base, r, u) ((base) + (r) * HROWB + (u) * 16)

__global__ __launch_bounds__(256)
void flash_mma(const __half* __restrict__ Qg, const __half* __restrict__ Kg,
               const __half* __restrict__ Vtg, __half* __restrict__ Og)
{
    extern __shared__ __align__(16) char fsm[];
    const uint32_t sb = smem_u32(fsm);
    const uint32_t sQ  = sb + QOFFB;
    const uint32_t sK0 = sb + KOFFB;
    const uint32_t sT0 = sb + TOFFB;
    const uint32_t sP  = sb + POFFB;
    __half* Ph = (__half*)(fsm + POFFB);

    const int tid = threadIdx.x;
    const int wid = tid >> 5, lane = tid & 31;
    const int g = lane >> 2, t = lane & 3;
    const int qt = (int)(gridDim.x - 1 - blockIdx.x);   // heavy CTAs first
    const int bh = blockIdx.y;
    const int b = bh >> 4, h = bh & 15;
    const int q0 = qt * 256;
    const int ktiles = 4 * qt + 4;
    const size_t base = (size_t)b * Tv * Cv + (size_t)h * Dv;
    const __half* vtb = Vtg + (size_t)bh * Dv * Tv;

    // prologue: Q + K/Vt tiles 0 and 1 (two commit groups)
    {
        const __half* qb = Qg + base + (size_t)q0 * Cv;
        #pragma unroll
        for (int i = 0; i < 8; i++) {
            int id = tid + i * 256, r = id >> 3, u = id & 7;
            cp16(HADDR(sQ, r, u), qb + (size_t)r * Cv + u * 8);
        }
        #pragma unroll
        for (int s = 0; s < 2; s++) {     // ktiles >= 4 always
            const __half* kb = Kg + base + (size_t)(s * 64) * Cv;
            const __half* vb = vtb + s * 64;
            #pragma unroll
            for (int i = 0; i < 2; i++) {
                int id = tid + i * 256, r = id >> 3, u = id & 7;
                cp16(HADDR(sK0 + s * KVTB, r, u), kb + (size_t)r * Cv + u * 8);
                cp16(HADDR(sT0 + s * KVTB, r, u), vb + (size_t)r * Tv + u * 8);
            }
            asm volatile("cp.async.commit_group;");
        }
    }

    float oacc[2][8][4];
    #pragma unroll
    for (int mf = 0; mf < 2; mf++)
        #pragma unroll
        for (int nf = 0; nf < 8; nf++)
            #pragma unroll
            for (int k = 0; k < 4; k++) oacc[mf][nf][k] = 0.f;
    float mrow[2][2], lrow[2][2];
    #pragma unroll
    for (int mf = 0; mf < 2; mf++) {
        mrow[mf][0] = -1e30f; mrow[mf][1] = -1e30f;
        lrow[mf][0] = 0.f;    lrow[mf][1] = 0.f;
    }
    uint32_t qf[2][4][4];

    for (int kt = 0; kt < ktiles; ++kt) {
        if (kt + 1 < ktiles) asm volatile("cp.async.wait_group 1;");
        else                 asm volatile("cp.async.wait_group 0;");
        __syncthreads();
        if (kt + 2 < ktiles) {      // prefetch tile kt+2 into ring slot
            int nb = (kt + 2) % 3;
            const __half* kb = Kg + base + (size_t)((kt + 2) * 64) * Cv;
            const __half* vb = vtb + (kt + 2) * 64;
            #pragma unroll
            for (int i = 0; i < 2; i++) {
                int id = tid + i * 256, r = id >> 3, u = id & 7;
                cp16(HADDR(sK0 + nb * KVTB, r, u), kb + (size_t)r * Cv + u * 8);
                cp16(HADDR(sT0 + nb * KVTB, r, u), vb + (size_t)r * Tv + u * 8);
            }
            asm volatile("cp.async.commit_group;");
        }
        if (kt == 0) {
            #pragma unroll
            for (int mf = 0; mf < 2; mf++)
                #pragma unroll
                for (int ks = 0; ks < 4; ks++) {
                    int row = wid * 32 + mf * 16 + (lane & 15);
                    int u = ks * 2 + (lane >> 4);
                    LDM_X4(qf[mf][ks][0], qf[mf][ks][1], qf[mf][ks][2], qf[mf][ks][3],
                           HADDR(sQ, row, u));
                }
        }
        const int cur = kt % 3;
        const uint32_t sKb = sK0 + cur * KVTB;
        const uint32_t sTb = sT0 + cur * KVTB;

        // ---- S = Q K^T
        float sacc[2][8][4];
        #pragma unroll
        for (int mf = 0; mf < 2; mf++)
            #pragma unroll
            for (int nf = 0; nf < 8; nf++)
                #pragma unroll
                for (int k = 0; k < 4; k++) sacc[mf][nf][k] = 0.f;

        #pragma unroll
        for (int ks = 0; ks < 4; ks++) {
            const int u0 = ks * 2;
            uint32_t bf[8][2];
            #pragma unroll
            for (int np = 0; np < 4; np++) {
                int row = np * 16 + ((lane & 16) >> 1) + (lane & 7);
                int u = u0 + ((lane & 8) >> 3);
                uint32_t r0, r1, r2, r3;
                LDM_X4(r0, r1, r2, r3, HADDR(sKb, row, u));
                bf[np*2+0][0] = r0; bf[np*2+0][1] = r1;
                bf[np*2+1][0] = r2; bf[np*2+1][1] = r3;
            }
            #pragma unroll
            for (int mf = 0; mf < 2; mf++)
                #pragma unroll
                for (int nf = 0; nf < 8; nf++)
                    mma_f16(sacc[mf][nf], qf[mf][ks], bf[nf]);
        }

        // ---- causal mask (band tiles only)
        if (kt >= 4 * qt) {
            const int k0 = kt * 64;
            #pragma unroll
            for (int mf = 0; mf < 2; mf++) {
                int r0g = q0 + wid * 32 + mf * 16 + g, r1g = r0g + 8;
                #pragma unroll
                for (int nf = 0; nf < 8; nf++) {
                    int c0 = k0 + nf * 8 + 2 * t;
                    if (c0     > r0g) sacc[mf][nf][0] = -1e30f;
                    if (c0 + 1 > r0g) sacc[mf][nf][1] = -1e30f;
                    if (c0     > r1g) sacc[mf][nf][2] = -1e30f;
                    if (c0 + 1 > r1g) sacc[mf][nf][3] = -1e30f;
                }
            }
        }

        // ---- online softmax (fp32; P rounded to fp16 before summation)
        #pragma unroll
        for (int mf = 0; mf < 2; mf++) {
            float mx0 = -1e30f, mx1 = -1e30f;
            #pragma unroll
            for (int nf = 0; nf < 8; nf++) {
                mx0 = fmaxf(mx0, fmaxf(sacc[mf][nf][0], sacc[mf][nf][1]));
                mx1 = fmaxf(mx1, fmaxf(sacc[mf][nf][2], sacc[mf][nf][3]));
            }
            #pragma unroll
            for (int off = 1; off < 4; off <<= 1) {
                mx0 = fmaxf(mx0, __shfl_xor_sync(0xffffffffu, mx0, off));
                mx1 = fmaxf(mx1, __shfl_xor_sync(0xffffffffu, mx1, off));
            }
            float nm0 = fmaxf(mrow[mf][0], mx0), nm1 = fmaxf(mrow[mf][1], mx1);
            float al0 = __expf(mrow[mf][0] - nm0), al1 = __expf(mrow[mf][1] - nm1);
            float rs0 = 0.f, rs1 = 0.f;
            #pragma unroll
            for (int nf = 0; nf < 8; nf++) {
                float p0 = __half2float(__float2half_rn(__expf(sacc[mf][nf][0] - nm0)));
                float p1 = __half2float(__float2half_rn(__expf(sacc[mf][nf][1] - nm0)));
                float p2 = __half2float(__float2half_rn(__expf(sacc[mf][nf][2] - nm1)));
                float p3 = __half2float(__float2half_rn(__expf(sacc[mf][nf][3] - nm1)));
                sacc[mf][nf][0] = p0; sacc[mf][nf][1] = p1;
                sacc[mf][nf][2] = p2; sacc[mf][nf][3] = p3;
                rs0 += p0 + p1; rs1 += p2 + p3;
            }
            #pragma unroll
            for (int off = 1; off < 4; off <<= 1) {
                rs0 += __shfl_xor_sync(0xffffffffu, rs0, off);
                rs1 += __shfl_xor_sync(0xffffffffu, rs1, off);
            }
            lrow[mf][0] = lrow[mf][0] * al0 + rs0; mrow[mf][0] = nm0;
            lrow[mf][1] = lrow[mf][1] * al1 + rs1; mrow[mf][1] = nm1;
            #pragma unroll
            for (int nf = 0; nf < 8; nf++) {
                oacc[mf][nf][0] *= al0; oacc[mf][nf][1] *= al0;
                oacc[mf][nf][2] *= al1; oacc[mf][nf][3] *= al1;
            }
        }

        // ---- P -> warp-private smem rows (fp16); own warp reads back
        __syncwarp();
        #pragma unroll
        for (int mf = 0; mf < 2; mf++) {
            int pr0 = wid * 32 + mf * 16 + g, pr1 = pr0 + 8;
            #pragma unroll
            for (int nf = 0; nf < 8; nf++) {
                *(__half2*)&Ph[pr0 * HPAD + nf * 8 + 2 * t] =
                    __floats2half2_rn(sacc[mf][nf][0], sacc[mf][nf][1]);
                *(__half2*)&Ph[pr1 * HPAD + nf * 8 + 2 * t] =
                    __floats2half2_rn(sacc[mf][nf][2], sacc[mf][nf][3]);
            }
        }
        __syncwarp();

        // ---- O += P V   (A = P, B = Vt tile, both via ldmatrix)
        #pragma unroll
        for (int ks = 0; ks < 4; ks++) {
            const int u0 = ks * 2;
            uint32_t af[2][4];
            #pragma unroll
            for (int mf = 0; mf < 2; mf++) {
                int row = wid * 32 + mf * 16 + (lane & 15);
                int u = u0 + (lane >> 4);
                LDM_X4(af[mf][0], af[mf][1], af[mf][2], af[mf][3], HADDR(sP, row, u));
            }
            uint32_t bf[8][2];
            #pragma unroll
            for (int np = 0; np < 4; np++) {
                int brow = np * 16 + ((lane & 16) >> 1) + (lane & 7);
                int u = u0 + ((lane & 8) >> 3);
                uint32_t r0, r1, r2, r3;
                LDM_X4(r0, r1, r2, r3, HADDR(sTb, brow, u));
                bf[np*2+0][0] = r0; bf[np*2+0][1] = r1;
                bf[np*2+1][0] = r2; bf[np*2+1][1] = r3;
            }
            #pragma unroll
            for (int mf = 0; mf < 2; mf++)
                #pragma unroll
                for (int nf = 0; nf < 8; nf++)
                    mma_f16(oacc[mf][nf], af[mf], bf[nf]);
        }
    }

    // ---- epilogue: normalize, write att as fp16
    #pragma unroll
    for (int mf = 0; mf < 2; mf++) {
        float inv0 = 1.f / lrow[mf][0], inv1 = 1.f / lrow[mf][1];
        int r0g = q0 + wid * 32 + mf * 16 + g, r1g = r0g + 8;
        #pragma unroll
        for (int nf = 0; nf < 8; nf++) {
            int c = nf * 8 + 2 * t;
            *(__half2*)(Og + base + (size_t)r0g * Cv + c) =
                __floats2half2_rn(oacc[mf][nf][0] * inv0, oacc[mf][nf][1] * inv0);
            *(__half2*)(Og + base + (size_t)r1g * Cv + c) =
                __floats2half2_rn(oacc[mf][nf][2] * inv1, oacc[mf][nf][3] * inv1);
        }
    }
}

// ---------------------------------------------------------------------------
extern "C" void kernel_launch(void* const* d_in, const int* in_sizes, int n_in,
                              void* d_out, int out_size)
{
    const float* x  = (const float*)d_in[0];
    const float* wq = (const float*)d_in[1];
    const float* wk = (const float*)d_in[2];
    const float* wv = (const float*)d_in[3];
    const float* wo = (const float*)d_in[4];
    float* out = (float*)d_out;

    __half *qp, *kp, *vtp, *ap, *xh, *wh;
    cudaGetSymbolAddress((void**)&qp, g_q);
    cudaGetSymbolAddress((void**)&kp, g_k);
    cudaGetSymbolAddress((void**)&vtp, g_vt);
    cudaGetSymbolAddress((void**)&ap, g_att);
    cudaGetSymbolAddress((void**)&xh, g_xh);
    cudaGetSymbolAddress((void**)&wh, g_wh);

    const int ntot = (Mv * Cv + 4 * Cv * Cv) / 4;
    round_all<<<(ntot + 255) / 256, 256>>>((const float4*)x,
                                           (const float4*)wq, (const float4*)wk,
                                           (const float4*)wv, (const float4*)wo,
                                           (__half2*)xh, (__half2*)wh);

    const int gsmem = 3 * STGB;   // 98304
    cudaFuncSetAttribute(gemm_h, cudaFuncAttributeMaxDynamicSharedMemorySize, gsmem);

    // fused QKV: Q pre-scaled 0.125; V written transposed into g_vt
    gemm_h<<<dim3(24, Mv/128), 256, gsmem>>>(xh, wh, qp, kp, vtp, 1);

    cudaFuncSetAttribute(flash_mma, cudaFuncAttributeMaxDynamicSharedMemorySize, FSMEM);
    flash_mma<<<dim3(Tv/256, Bv*Hv), 256, FSMEM>>>(qp, kp, vtp, ap);

    gemm_h<<<dim3(8, Mv/128), 256, gsmem>>>(ap, wh + 3*(size_t)Cv*Cv, out,
                                            nullptr, nullptr, 0);
}

// round 16
// speedup vs baseline: 1.0706x; 1.0215x over previous
#include <cuda_runtime.h>
#include <cuda_fp16.h>
#include <cstdint>
#include <math.h>

#define Bv 4
#define Tv 2048
#define Cv 1024
#define Hv 16
#define Dv 64
#define Mv (Bv*Tv)          // 8192 rows

// ---------------- scratch (device globals; no allocations allowed) ----------
__device__ __half g_q[Mv*Cv];
__device__ __half g_k[Mv*Cv];
__device__ __half g_vt[Bv*Hv*Dv*Tv];   // V transposed per (b,h): [d][t]
__device__ __half g_att[Mv*Cv];
__device__ __half g_xh[Mv*Cv];         // fp16 x
__device__ __half g_wh[4*Cv*Cv];       // fp16 wq,wk,wv,wo (contiguous)

__device__ __forceinline__ uint32_t smem_u32(const void* p) {
    uint32_t a;
    asm("{ .reg .u64 t; cvta.to.shared.u64 t, %1; cvt.u32.u64 %0, t; }"
        : "=r"(a) : "l"(p));
    return a;
}
__device__ __forceinline__ void cp16(uint32_t saddr, const void* gaddr) {
    asm volatile("cp.async.cg.shared.global [%0], [%1], 16;"
                 :: "r"(saddr), "l"(gaddr));
}
__device__ __forceinline__ void mma_f16(float* d, const uint32_t* a, const uint32_t* b) {
    asm volatile("mma.sync.aligned.m16n8k16.row.col.f32.f16.f16.f32 "
                 "{%0,%1,%2,%3}, {%4,%5,%6,%7}, {%8,%9}, {%0,%1,%2,%3};"
                 : "+f"(d[0]), "+f"(d[1]), "+f"(d[2]), "+f"(d[3])
                 : "r"(a[0]), "r"(a[1]), "r"(a[2]), "r"(a[3]), "r"(b[0]), "r"(b[1]));
}
#define LDM_X4(r0,r1,r2,r3, addr) \
    asm volatile("ldmatrix.sync.aligned.m8n8.x4.shared.b16 {%0,%1,%2,%3}, [%4];" \
                 : "=r"(r0),"=r"(r1),"=r"(r2),"=r"(r3) : "r"(addr))

// ---------------------------------------------------------------------------
// single-launch rounding to fp16: x (Mv*Cv) then wq|wk|wv|wo into g_xh/g_wh
// ---------------------------------------------------------------------------
__global__ void round_all(const float4* __restrict__ x,
                          const float4* __restrict__ w0, const float4* __restrict__ w1,
                          const float4* __restrict__ w2, const float4* __restrict__ w3,
                          __half2* __restrict__ xh, __half2* __restrict__ wh)
{
    const int nx = Mv * Cv / 4;
    const int per = Cv * Cv / 4;
    int i = blockIdx.x * blockDim.x + threadIdx.x;
    float4 v; __half2* dst;
    if (i < nx) {
        v = x[i]; dst = xh + 2 * i;
    } else {
        int j = i - nx;
        if (j >= 4 * per) return;
        const float4* src = (j < per) ? w0 : (j < 2*per) ? w1 : (j < 3*per) ? w2 : w3;
        v = src[j & (per - 1)];
        dst = wh + 2 * j;
    }
    dst[0] = __floats2half2_rn(v.x, v.y);
    dst[1] = __floats2half2_rn(v.z, v.w);
}

// ---------------------------------------------------------------------------
// fp16 mma.sync GEMM (m16n8k16):  C[M,N] = A[M,K] · B[N,K]^T    [R13 config]
// CTA 128x128, BK=64 (128B fp16 rows), 256 thr, 3-stage cp.async pipeline,
// XOR-swizzled smem (98304 B) -> 2 CTAs/SM. 16 K-iterations.
// qkv mode: n-block 0-7 -> Q (scaled 0.125*log2e -> log2-domain scores),
// 8-15 -> K, 16-23 -> V transposed into g_vt.
// ---------------------------------------------------------------------------
#define GBK   64
#define ABUF  16384              // 128 rows * 128 B
#define STGB  (2*ABUF)
#define NITER (Cv/GBK)           // 16
#define SWA(base, r, u) ((base) + (r) * 128 + (((u) ^ ((r) & 7)) << 4))
#define QSCALE 0.18033688011112042f   // 0.125 * log2(e)

__global__ __launch_bounds__(256, 2)
void gemm_h(const __half* __restrict__ A, const __half* __restrict__ B,
            void* __restrict__ C0v, void* __restrict__ C1v,
            void* __restrict__ C2v, int qkv)
{
    extern __shared__ __align__(128) char smem[];
    const uint32_t sb = smem_u32(smem);
    const int tid  = threadIdx.x;
    const int wid  = tid >> 5;
    const int lane = tid & 31;
    const int m0 = blockIdx.y * 128, n0 = blockIdx.x * 128;
    const int wm = (wid >> 2) * 64;
    const int wn = (wid & 3) * 32;
    const int lr = tid >> 3;
    const int lu = tid & 7;
    const int lc = lu * 8;
    const int kph = ((blockIdx.x ^ blockIdx.y) & 1) * (NITER / 2);

    float acc[4][4][4];
    #pragma unroll
    for (int i = 0; i < 4; i++)
        #pragma unroll
        for (int j = 0; j < 4; j++)
            #pragma unroll
            for (int k = 0; k < 4; k++) acc[i][j][k] = 0.f;

    #pragma unroll
    for (int s = 0; s < 2; s++) {
        const int kc = ((s + kph) & (NITER - 1)) * GBK;
        const uint32_t sA = sb + s * STGB, sB2 = sA + ABUF;
        #pragma unroll
        for (int i = 0; i < 4; i++) {
            int r = lr + i * 32;
            cp16(SWA(sA,  r, lu), A + (size_t)(m0 + r) * Cv + kc + lc);
            cp16(SWA(sB2, r, lu), B + (size_t)(n0 + r) * Cv + kc + lc);
        }
        asm volatile("cp.async.commit_group;");
    }

    for (int it = 0; it < NITER; ++it) {
        if (it < NITER - 1) asm volatile("cp.async.wait_group 1;");
        else                asm volatile("cp.async.wait_group 0;");
        __syncthreads();

        if (it + 2 < NITER) {
            const int kc = ((it + 2 + kph) & (NITER - 1)) * GBK;
            const uint32_t db = sb + ((it + 2) % 3) * STGB;
            const uint32_t dA = db, dB = db + ABUF;
            #pragma unroll
            for (int i = 0; i < 4; i++) {
                int r = lr + i * 32;
                cp16(SWA(dA, r, lu), A + (size_t)(m0 + r) * Cv + kc + lc);
                cp16(SWA(dB, r, lu), B + (size_t)(n0 + r) * Cv + kc + lc);
            }
            asm volatile("cp.async.commit_group;");
        }

        const uint32_t base = sb + (it % 3) * STGB;
        const uint32_t sA = base, sB = base + ABUF;

        #pragma unroll
        for (int ks = 0; ks < 4; ++ks) {
            const int u0 = ks * 2;
            uint32_t af[4][4], bf[4][2];
            #pragma unroll
            for (int mf = 0; mf < 4; ++mf) {
                int row = wm + mf * 16 + (lane & 15);
                int u = u0 + (lane >> 4);
                LDM_X4(af[mf][0], af[mf][1], af[mf][2], af[mf][3], SWA(sA, row, u));
            }
            #pragma unroll
            for (int np = 0; np < 2; ++np) {
                int row = wn + np * 16 + ((lane & 16) >> 1) + (lane & 7);
                int u = u0 + ((lane & 8) >> 3);
                uint32_t r0, r1, r2, r3;
                LDM_X4(r0, r1, r2, r3, SWA(sB, row, u));
                bf[np*2+0][0] = r0; bf[np*2+0][1] = r1;
                bf[np*2+1][0] = r2; bf[np*2+1][1] = r3;
            }
            #pragma unroll
            for (int mf = 0; mf < 4; ++mf)
                #pragma unroll
                for (int nf = 0; nf < 4; ++nf)
                    mma_f16(acc[mf][nf], af[mf], bf[nf]);
        }
    }

    const int rA = lane >> 2;
    const int cA = (lane & 3) * 2;

    if (qkv) {
        if (n0 >= 2048) {
            __half* C2 = (__half*)C2v;
            #pragma unroll
            for (int mf = 0; mf < 4; ++mf)
                #pragma unroll
                for (int nf = 0; nf < 4; ++nf) {
                    int row = m0 + wm + mf * 16 + rA;
                    int col = (n0 - 2048) + wn + nf * 8 + cA;
                    int b2 = row >> 11, t2 = row & 2047;
                    int h2 = col >> 6, d2 = col & 63;
                    __half* vb = C2 + ((size_t)((b2 * 16 + h2) * 64 + d2)) * Tv + t2;
                    vb[0]      = __float2half_rn(acc[mf][nf][0]);
                    vb[Tv]     = __float2half_rn(acc[mf][nf][1]);
                    vb[8]      = __float2half_rn(acc[mf][nf][2]);
                    vb[Tv + 8] = __float2half_rn(acc[mf][nf][3]);
                }
            return;
        }
        __half* C = (n0 >= 1024) ? (__half*)C1v : (__half*)C0v;
        const int nn = n0 & 1023;
        const float sc = (n0 < 1024) ? QSCALE : 1.0f;   // Q in log2 domain
        #pragma unroll
        for (int mf = 0; mf < 4; ++mf)
            #pragma unroll
            for (int nf = 0; nf < 4; ++nf) {
                int row = m0 + wm + mf * 16 + rA;
                int col = nn + wn + nf * 8 + cA;
                *(__half2*)(C + (size_t)row * Cv + col) =
                    __floats2half2_rn(acc[mf][nf][0] * sc, acc[mf][nf][1] * sc);
                *(__half2*)(C + (size_t)(row + 8) * Cv + col) =
                    __floats2half2_rn(acc[mf][nf][2] * sc, acc[mf][nf][3] * sc);
            }
        return;
    }

    float* C = (float*)C0v;
    #pragma unroll
    for (int mf = 0; mf < 4; ++mf)
        #pragma unroll
        for (int nf = 0; nf < 4; ++nf) {
            int row = m0 + wm + mf * 16 + rA;
            int col = n0 + wn + nf * 8 + cA;
            *(float2*)(C + (size_t)row * Cv + col) =
                make_float2(acc[mf][nf][0], acc[mf][nf][1]);
            *(float2*)(C + (size_t)(row + 8) * Cv + col) =
                make_float2(acc[mf][nf][2], acc[mf][nf][3]);
        }
}

// ---------------------------------------------------------------------------
// Causal flash attention, fp16 m16n8k16 — BM=256 (8 warps x 32 q-rows), BN=64.
// Scores arrive in log2 domain; softmax via h2exp2 (fp16x2 MUFU, half pressure).
// K and Vt double-buffered via cp.async; one barrier per tile. smem 110592 B.
// ---------------------------------------------------------------------------
#define HPAD  72
#define HROWB (HPAD*2)            // 144 B per row
#define KVTB  (64*HROWB)          // 9216 B per K/V tile
#define QOFFB 0
#define KOFFB (256*HROWB)         // 36864
#define TOFFB (KOFFB + 2*KVTB)    // 55296
#define POFFB (TOFFB + 2*KVTB)    // 73728
#define FSMEM (POFFB + 256*HROWB) // 110592 B
#define HADDR(base, r, u) ((base) + (r) * HROWB + (u) * 16)

__global__ __launch_bounds__(256)
void flash_mma(const __half* __restrict__ Qg, const __half* __restrict__ Kg,
               const __half* __restrict__ Vtg, __half* __restrict__ Og)
{
    extern __shared__ __align__(16) char fsm[];
    const uint32_t sb = smem_u32(fsm);
    const uint32_t sQ  = sb + QOFFB;
    const uint32_t sK0 = sb + KOFFB;
    const uint32_t sT0 = sb + TOFFB;
    const uint32_t sP  = sb + POFFB;
    __half* Ph = (__half*)(fsm + POFFB);

    const int tid = threadIdx.x;
    const int wid = tid >> 5, lane = tid & 31;
    const int g = lane >> 2, t = lane & 3;
    const int qt = (int)(gridDim.x - 1 - blockIdx.x);   // heavy CTAs first
    const int bh = blockIdx.y;
    const int b = bh >> 4, h = bh & 15;
    const int q0 = qt * 256;
    const int ktiles = 4 * qt + 4;
    const size_t base = (size_t)b * Tv * Cv + (size_t)h * Dv;
    const __half* vtb = Vtg + (size_t)bh * Dv * Tv;

    {
        const __half* qb = Qg + base + (size_t)q0 * Cv;
        const __half* kb = Kg + base;
        #pragma unroll
        for (int i = 0; i < 8; i++) {
            int id = tid + i * 256, r = id >> 3, u = id & 7;
            cp16(HADDR(sQ, r, u), qb + (size_t)r * Cv + u * 8);
        }
        #pragma unroll
        for (int i = 0; i < 2; i++) {
            int id = tid + i * 256, r = id >> 3, u = id & 7;
            cp16(HADDR(sK0, r, u), kb + (size_t)r * Cv + u * 8);
            cp16(HADDR(sT0, r, u), vtb + (size_t)r * Tv + u * 8);
        }
        asm volatile("cp.async.commit_group;");
    }

    float oacc[2][8][4];
    #pragma unroll
    for (int mf = 0; mf < 2; mf++)
        #pragma unroll
        for (int nf = 0; nf < 8; nf++)
            #pragma unroll
            for (int k = 0; k < 4; k++) oacc[mf][nf][k] = 0.f;
    float mrow[2][2], lrow[2][2];
    #pragma unroll
    for (int mf = 0; mf < 2; mf++) {
        mrow[mf][0] = -1e30f; mrow[mf][1] = -1e30f;
        lrow[mf][0] = 0.f;    lrow[mf][1] = 0.f;
    }
    uint32_t qf[2][4][4];

    for (int kt = 0; kt < ktiles; ++kt) {
        const int cur = kt & 1;
        asm volatile("cp.async.wait_group 0;");
        __syncthreads();
        if (kt + 1 < ktiles) {
            int nb = cur ^ 1;
            const __half* kb = Kg + base + (size_t)((kt + 1) * 64) * Cv;
            const __half* vb = vtb + (kt + 1) * 64;
            #pragma unroll
            for (int i = 0; i < 2; i++) {
                int id = tid + i * 256, r = id >> 3, u = id & 7;
                cp16(HADDR(sK0 + nb * KVTB, r, u), kb + (size_t)r * Cv + u * 8);
                cp16(HADDR(sT0 + nb * KVTB, r, u), vb + (size_t)r * Tv + u * 8);
            }
            asm volatile("cp.async.commit_group;");
        }
        if (kt == 0) {
            #pragma unroll
            for (int mf = 0; mf < 2; mf++)
                #pragma unroll
                for (int ks = 0; ks < 4; ks++) {
                    int row = wid * 32 + mf * 16 + (lane & 15);
                    int u = ks * 2 + (lane >> 4);
                    LDM_X4(qf[mf][ks][0], qf[mf][ks][1], qf[mf][ks][2], qf[mf][ks][3],
                           HADDR(sQ, row, u));
                }
        }
        const uint32_t sKb = sK0 + cur * KVTB;
        const uint32_t sTb = sT0 + cur * KVTB;

        // ---- S = Q K^T  (scores in log2 domain)
        float sacc[2][8][4];
        #pragma unroll
        for (int mf = 0; mf < 2; mf++)
            #pragma unroll
            for (int nf = 0; nf < 8; nf++)
                #pragma unroll
                for (int k = 0; k < 4; k++) sacc[mf][nf][k] = 0.f;

        #pragma unroll
        for (int ks = 0; ks < 4; ks++) {
            const int u0 = ks * 2;
            uint32_t bf[8][2];
            #pragma unroll
            for (int np = 0; np < 4; np++) {
                int row = np * 16 + ((lane & 16) >> 1) + (lane & 7);
                int u = u0 + ((lane & 8) >> 3);
                uint32_t r0, r1, r2, r3;
                LDM_X4(r0, r1, r2, r3, HADDR(sKb, row, u));
                bf[np*2+0][0] = r0; bf[np*2+0][1] = r1;
                bf[np*2+1][0] = r2; bf[np*2+1][1] = r3;
            }
            #pragma unroll
            for (int mf = 0; mf < 2; mf++)
                #pragma unroll
                for (int nf = 0; nf < 8; nf++)
                    mma_f16(sacc[mf][nf], qf[mf][ks], bf[nf]);
        }

        // ---- causal mask (band tiles only)
        if (kt >= 4 * qt) {
            const int k0 = kt * 64;
            #pragma unroll
            for (int mf = 0; mf < 2; mf++) {
                int r0g = q0 + wid * 32 + mf * 16 + g, r1g = r0g + 8;
                #pragma unroll
                for (int nf = 0; nf < 8; nf++) {
                    int c0 = k0 + nf * 8 + 2 * t;
                    if (c0     > r0g) sacc[mf][nf][0] = -1e30f;
                    if (c0 + 1 > r0g) sacc[mf][nf][1] = -1e30f;
                    if (c0     > r1g) sacc[mf][nf][2] = -1e30f;
                    if (c0 + 1 > r1g) sacc[mf][nf][3] = -1e30f;
                }
            }
        }

        // ---- online softmax in log2 domain: p = exp2(s - m) via h2exp2
        __half2 pk[2][8][2];   // packed P fragments (rows g / g+8)
        #pragma unroll
        for (int mf = 0; mf < 2; mf++) {
            float mx0 = -1e30f, mx1 = -1e30f;
            #pragma unroll
            for (int nf = 0; nf < 8; nf++) {
                mx0 = fmaxf(mx0, fmaxf(sacc[mf][nf][0], sacc[mf][nf][1]));
                mx1 = fmaxf(mx1, fmaxf(sacc[mf][nf][2], sacc[mf][nf][3]));
            }
            #pragma unroll
            for (int off = 1; off < 4; off <<= 1) {
                mx0 = fmaxf(mx0, __shfl_xor_sync(0xffffffffu, mx0, off));
                mx1 = fmaxf(mx1, __shfl_xor_sync(0xffffffffu, mx1, off));
            }
            float nm0 = fmaxf(mrow[mf][0], mx0), nm1 = fmaxf(mrow[mf][1], mx1);
            float al0 = exp2f(mrow[mf][0] - nm0), al1 = exp2f(mrow[mf][1] - nm1);
            float rs0 = 0.f, rs1 = 0.f;
            #pragma unroll
            for (int nf = 0; nf < 8; nf++) {
                __half2 p01 = h2exp2(__floats2half2_rn(sacc[mf][nf][0] - nm0,
                                                       sacc[mf][nf][1] - nm0));
                __half2 p23 = h2exp2(__floats2half2_rn(sacc[mf][nf][2] - nm1,
                                                       sacc[mf][nf][3] - nm1));
                pk[mf][nf][0] = p01; pk[mf][nf][1] = p23;
                float2 f01 = __half22float2(p01);
                float2 f23 = __half22float2(p23);
                rs0 += f01.x + f01.y;
                rs1 += f23.x + f23.y;
            }
            #pragma unroll
            for (int off = 1; off < 4; off <<= 1) {
                rs0 += __shfl_xor_sync(0xffffffffu, rs0, off);
                rs1 += __shfl_xor_sync(0xffffffffu, rs1, off);
            }
            lrow[mf][0] = lrow[mf][0] * al0 + rs0; mrow[mf][0] = nm0;
            lrow[mf][1] = lrow[mf][1] * al1 + rs1; mrow[mf][1] = nm1;
            #pragma unroll
            for (int nf = 0; nf < 8; nf++) {
                oacc[mf][nf][0] *= al0; oacc[mf][nf][1] *= al0;
                oacc[mf][nf][2] *= al1; oacc[mf][nf][3] *= al1;
            }
        }

        // ---- P -> warp-private smem rows (already fp16x2 packed)
        __syncwarp();
        #pragma unroll
        for (int mf = 0; mf < 2; mf++) {
            int pr0 = wid * 32 + mf * 16 + g, pr1 = pr0 + 8;
            #pragma unroll
            for (int nf = 0; nf < 8; nf++) {
                *(__half2*)&Ph[pr0 * HPAD + nf * 8 + 2 * t] = pk[mf][nf][0];
                *(__half2*)&Ph[pr1 * HPAD + nf * 8 + 2 * t] = pk[mf][nf][1];
            }
        }
        __syncwarp();

        // ---- O += P V   (A = P, B = Vt tile, both via ldmatrix)
        #pragma unroll
        for (int ks = 0; ks < 4; ks++) {
            const int u0 = ks * 2;
            uint32_t af[2][4];
            #pragma unroll
            for (int mf = 0; mf < 2; mf++) {
                int row = wid * 32 + mf * 16 + (lane & 15);
                int u = u0 + (lane >> 4);
                LDM_X4(af[mf][0], af[mf][1], af[mf][2], af[mf][3], HADDR(sP, row, u));
            }
            uint32_t bf[8][2];
            #pragma unroll
            for (int np = 0; np < 4; np++) {
                int brow = np * 16 + ((lane & 16) >> 1) + (lane & 7);
                int u = u0 + ((lane & 8) >> 3);
                uint32_t r0, r1, r2, r3;
                LDM_X4(r0, r1, r2, r3, HADDR(sTb, brow, u));
                bf[np*2+0][0] = r0; bf[np*2+0][1] = r1;
                bf[np*2+1][0] = r2; bf[np*2+1][1] = r3;
            }
            #pragma unroll
            for (int mf = 0; mf < 2; mf++)
                #pragma unroll
                for (int nf = 0; nf < 8; nf++)
                    mma_f16(oacc[mf][nf], af[mf], bf[nf]);
        }
    }

    // ---- epilogue: normalize, write att as fp16
    #pragma unroll
    for (int mf = 0; mf < 2; mf++) {
        float inv0 = 1.f / lrow[mf][0], inv1 = 1.f / lrow[mf][1];
        int r0g = q0 + wid * 32 + mf * 16 + g, r1g = r0g + 8;
        #pragma unroll
        for (int nf = 0; nf < 8; nf++) {
            int c = nf * 8 + 2 * t;
            *(__half2*)(Og + base + (size_t)r0g * Cv + c) =
                __floats2half2_rn(oacc[mf][nf][0] * inv0, oacc[mf][nf][1] * inv0);
            *(__half2*)(Og + base + (size_t)r1g * Cv + c) =
                __floats2half2_rn(oacc[mf][nf][2] * inv1, oacc[mf][nf][3] * inv1);
        }
    }
}

// ---------------------------------------------------------------------------
extern "C" void kernel_launch(void* const* d_in, const int* in_sizes, int n_in,
                              void* d_out, int out_size)
{
    const float* x  = (const float*)d_in[0];
    const float* wq = (const float*)d_in[1];
    const float* wk = (const float*)d_in[2];
    const float* wv = (const float*)d_in[3];
    const float* wo = (const float*)d_in[4];
    float* out = (float*)d_out;

    __half *qp, *kp, *vtp, *ap, *xh, *wh;
    cudaGetSymbolAddress((void**)&qp, g_q);
    cudaGetSymbolAddress((void**)&kp, g_k);
    cudaGetSymbolAddress((void**)&vtp, g_vt);
    cudaGetSymbolAddress((void**)&ap, g_att);
    cudaGetSymbolAddress((void**)&xh, g_xh);
    cudaGetSymbolAddress((void**)&wh, g_wh);

    const int ntot = (Mv * Cv + 4 * Cv * Cv) / 4;
    round_all<<<(ntot + 255) / 256, 256>>>((const float4*)x,
                                           (const float4*)wq, (const float4*)wk,
                                           (const float4*)wv, (const float4*)wo,
                                           (__half2*)xh, (__half2*)wh);

    const int gsmem = 3 * STGB;   // 98304
    cudaFuncSetAttribute(gemm_h, cudaFuncAttributeMaxDynamicSharedMemorySize, gsmem);

    // fused QKV: Q pre-scaled 0.125*log2e; V written transposed into g_vt
    gemm_h<<<dim3(24, Mv/128), 256, gsmem>>>(xh, wh, qp, kp, vtp, 1);

    cudaFuncSetAttribute(flash_mma, cudaFuncAttributeMaxDynamicSharedMemorySize, FSMEM);
    flash_mma<<<dim3(Tv/256, Bv*Hv), 256, FSMEM>>>(qp, kp, vtp, ap);

    gemm_h<<<dim3(8, Mv/128), 256, gsmem>>>(ap, wh + 3*(size_t)Cv*Cv, out,
                                            nullptr, nullptr, 0);
}

// round 17
// speedup vs baseline: 1.0937x; 1.0216x over previous
#include <cuda_runtime.h>
#include <cuda_fp16.h>
#include <cstdint>
#include <math.h>

#define Bv 4
#define Tv 2048
#define Cv 1024
#define Hv 16
#define Dv 64
#define Mv (Bv*Tv)          // 8192 rows

// ---------------- scratch (device globals; no allocations allowed) ----------
__device__ __half g_q[Mv*Cv];
__device__ __half g_k[Mv*Cv];
__device__ __half g_vt[Bv*Hv*Dv*Tv];   // V transposed per (b,h): [d][t]
__device__ __half g_att[Mv*Cv];
__device__ __half g_xh[Mv*Cv];         // fp16 x
__device__ __half g_wh[4*Cv*Cv];       // fp16 wq,wk,wv,wo (contiguous)

__device__ __forceinline__ uint32_t smem_u32(const void* p) {
    uint32_t a;
    asm("{ .reg .u64 t; cvta.to.shared.u64 t, %1; cvt.u32.u64 %0, t; }"
        : "=r"(a) : "l"(p));
    return a;
}
__device__ __forceinline__ void cp16(uint32_t saddr, const void* gaddr) {
    asm volatile("cp.async.cg.shared.global [%0], [%1], 16;"
                 :: "r"(saddr), "l"(gaddr));
}
__device__ __forceinline__ void mma_f16(float* d, const uint32_t* a, const uint32_t* b) {
    asm volatile("mma.sync.aligned.m16n8k16.row.col.f32.f16.f16.f32 "
                 "{%0,%1,%2,%3}, {%4,%5,%6,%7}, {%8,%9}, {%0,%1,%2,%3};"
                 : "+f"(d[0]), "+f"(d[1]), "+f"(d[2]), "+f"(d[3])
                 : "r"(a[0]), "r"(a[1]), "r"(a[2]), "r"(a[3]), "r"(b[0]), "r"(b[1]));
}
#define LDM_X4(r0,r1,r2,r3, addr) \
    asm volatile("ldmatrix.sync.aligned.m8n8.x4.shared.b16 {%0,%1,%2,%3}, [%4];" \
                 : "=r"(r0),"=r"(r1),"=r"(r2),"=r"(r3) : "r"(addr))
#define GBAR(id) asm volatile("bar.sync %0, 128;" :: "r"(id) : "memory")

// ---------------------------------------------------------------------------
// single-launch rounding to fp16: x (Mv*Cv) then wq|wk|wv|wo into g_xh/g_wh
// ---------------------------------------------------------------------------
__global__ void round_all(const float4* __restrict__ x,
                          const float4* __restrict__ w0, const float4* __restrict__ w1,
                          const float4* __restrict__ w2, const float4* __restrict__ w3,
                          __half2* __restrict__ xh, __half2* __restrict__ wh)
{
    const int nx = Mv * Cv / 4;
    const int per = Cv * Cv / 4;
    int i = blockIdx.x * blockDim.x + threadIdx.x;
    float4 v; __half2* dst;
    if (i < nx) {
        v = x[i]; dst = xh + 2 * i;
    } else {
        int j = i - nx;
        if (j >= 4 * per) return;
        const float4* src = (j < per) ? w0 : (j < 2*per) ? w1 : (j < 3*per) ? w2 : w3;
        v = src[j & (per - 1)];
        dst = wh + 2 * j;
    }
    dst[0] = __floats2half2_rn(v.x, v.y);
    dst[1] = __floats2half2_rn(v.z, v.w);
}

// ---------------------------------------------------------------------------
// fp16 mma.sync GEMM (m16n8k16):  C[M,N] = A[M,K] · B[N,K]^T    [R13 config]
// CTA 128x128, BK=64, 256 thr, 3-stage cp.async pipeline, XOR swizzle,
// 98304 B smem -> 2 CTAs/SM.
// qkv mode: n-block 0-7 -> Q (scaled 0.125*log2e), 8-15 -> K, 16-23 -> V^T.
// ---------------------------------------------------------------------------
#define GBK   64
#define ABUF  16384
#define STGB  (2*ABUF)
#define NITER (Cv/GBK)
#define SWA(base, r, u) ((base) + (r) * 128 + (((u) ^ ((r) & 7)) << 4))
#define QSCALE 0.18033688011112042f   // 0.125 * log2(e)

__global__ __launch_bounds__(256, 2)
void gemm_h(const __half* __restrict__ A, const __half* __restrict__ B,
            void* __restrict__ C0v, void* __restrict__ C1v,
            void* __restrict__ C2v, int qkv)
{
    extern __shared__ __align__(128) char smem[];
    const uint32_t sb = smem_u32(smem);
    const int tid  = threadIdx.x;
    const int wid  = tid >> 5;
    const int lane = tid & 31;
    const int m0 = blockIdx.y * 128, n0 = blockIdx.x * 128;
    const int wm = (wid >> 2) * 64;
    const int wn = (wid & 3) * 32;
    const int lr = tid >> 3;
    const int lu = tid & 7;
    const int lc = lu * 8;
    const int kph = ((blockIdx.x ^ blockIdx.y) & 1) * (NITER / 2);

    float acc[4][4][4];
    #pragma unroll
    for (int i = 0; i < 4; i++)
        #pragma unroll
        for (int j = 0; j < 4; j++)
            #pragma unroll
            for (int k = 0; k < 4; k++) acc[i][j][k] = 0.f;

    #pragma unroll
    for (int s = 0; s < 2; s++) {
        const int kc = ((s + kph) & (NITER - 1)) * GBK;
        const uint32_t sA = sb + s * STGB, sB2 = sA + ABUF;
        #pragma unroll
        for (int i = 0; i < 4; i++) {
            int r = lr + i * 32;
            cp16(SWA(sA,  r, lu), A + (size_t)(m0 + r) * Cv + kc + lc);
            cp16(SWA(sB2, r, lu), B + (size_t)(n0 + r) * Cv + kc + lc);
        }
        asm volatile("cp.async.commit_group;");
    }

    for (int it = 0; it < NITER; ++it) {
        if (it < NITER - 1) asm volatile("cp.async.wait_group 1;");
        else                asm volatile("cp.async.wait_group 0;");
        __syncthreads();

        if (it + 2 < NITER) {
            const int kc = ((it + 2 + kph) & (NITER - 1)) * GBK;
            const uint32_t db = sb + ((it + 2) % 3) * STGB;
            const uint32_t dA = db, dB = db + ABUF;
            #pragma unroll
            for (int i = 0; i < 4; i++) {
                int r = lr + i * 32;
                cp16(SWA(dA, r, lu), A + (size_t)(m0 + r) * Cv + kc + lc);
                cp16(SWA(dB, r, lu), B + (size_t)(n0 + r) * Cv + kc + lc);
            }
            asm volatile("cp.async.commit_group;");
        }

        const uint32_t base = sb + (it % 3) * STGB;
        const uint32_t sA = base, sB = base + ABUF;

        #pragma unroll
        for (int ks = 0; ks < 4; ++ks) {
            const int u0 = ks * 2;
            uint32_t af[4][4], bf[4][2];
            #pragma unroll
            for (int mf = 0; mf < 4; ++mf) {
                int row = wm + mf * 16 + (lane & 15);
                int u = u0 + (lane >> 4);
                LDM_X4(af[mf][0], af[mf][1], af[mf][2], af[mf][3], SWA(sA, row, u));
            }
            #pragma unroll
            for (int np = 0; np < 2; ++np) {
                int row = wn + np * 16 + ((lane & 16) >> 1) + (lane & 7);
                int u = u0 + ((lane & 8) >> 3);
                uint32_t r0, r1, r2, r3;
                LDM_X4(r0, r1, r2, r3, SWA(sB, row, u));
                bf[np*2+0][0] = r0; bf[np*2+0][1] = r1;
                bf[np*2+1][0] = r2; bf[np*2+1][1] = r3;
            }
            #pragma unroll
            for (int mf = 0; mf < 4; ++mf)
                #pragma unroll
                for (int nf = 0; nf < 4; ++nf)
                    mma_f16(acc[mf][nf], af[mf], bf[nf]);
        }
    }

    const int rA = lane >> 2;
    const int cA = (lane & 3) * 2;

    if (qkv) {
        if (n0 >= 2048) {
            __half* C2 = (__half*)C2v;
            #pragma unroll
            for (int mf = 0; mf < 4; ++mf)
                #pragma unroll
                for (int nf = 0; nf < 4; ++nf) {
                    int row = m0 + wm + mf * 16 + rA;
                    int col = (n0 - 2048) + wn + nf * 8 + cA;
                    int b2 = row >> 11, t2 = row & 2047;
                    int h2 = col >> 6, d2 = col & 63;
                    __half* vb = C2 + ((size_t)((b2 * 16 + h2) * 64 + d2)) * Tv + t2;
                    vb[0]      = __float2half_rn(acc[mf][nf][0]);
                    vb[Tv]     = __float2half_rn(acc[mf][nf][1]);
                    vb[8]      = __float2half_rn(acc[mf][nf][2]);
                    vb[Tv + 8] = __float2half_rn(acc[mf][nf][3]);
                }
            return;
        }
        __half* C = (n0 >= 1024) ? (__half*)C1v : (__half*)C0v;
        const int nn = n0 & 1023;
        const float sc = (n0 < 1024) ? QSCALE : 1.0f;
        #pragma unroll
        for (int mf = 0; mf < 4; ++mf)
            #pragma unroll
            for (int nf = 0; nf < 4; ++nf) {
                int row = m0 + wm + mf * 16 + rA;
                int col = nn + wn + nf * 8 + cA;
                *(__half2*)(C + (size_t)row * Cv + col) =
                    __floats2half2_rn(acc[mf][nf][0] * sc, acc[mf][nf][1] * sc);
                *(__half2*)(C + (size_t)(row + 8) * Cv + col) =
                    __floats2half2_rn(acc[mf][nf][2] * sc, acc[mf][nf][3] * sc);
            }
        return;
    }

    float* C = (float*)C0v;
    #pragma unroll
    for (int mf = 0; mf < 4; ++mf)
        #pragma unroll
        for (int nf = 0; nf < 4; ++nf) {
            int row = m0 + wm + mf * 16 + rA;
            int col = n0 + wn + nf * 8 + cA;
            *(float2*)(C + (size_t)row * Cv + col) =
                make_float2(acc[mf][nf][0], acc[mf][nf][1]);
            *(float2*)(C + (size_t)(row + 8) * Cv + col) =
                make_float2(acc[mf][nf][2], acc[mf][nf][3]);
        }
}

// ---------------------------------------------------------------------------
// Causal flash attention, fp16 m16n8k16, BM=256 split into TWO independent
// 4-warp groups (warps 0-3: q-rows [0,128), warps 4-7: [128,256)).
// Each group: own K/Vt double buffer, own named barrier (bar.sync 1+wg, 128).
// Groups drift freely -> one group's MMA covers the other's softmax stalls.
// Scores arrive in log2 domain; softmax via h2exp2.
// smem: Q[256] 36864 | K[4] 36864 | Vt[4] 36864 | P[256] 36864 = 147456 B
// ---------------------------------------------------------------------------
#define HPAD  72
#define HROWB (HPAD*2)            // 144 B per row
#define KVTB  (64*HROWB)          // 9216 B per K/V tile
#define QOFFB 0
#define KOFFB (256*HROWB)         // 36864
#define TOFFB (KOFFB + 4*KVTB)    // 73728
#define POFFB (TOFFB + 4*KVTB)    // 110592
#define FSMEM (POFFB + 256*HROWB) // 147456 B
#define HADDR(base, r, u) ((base) + (r) * HROWB + (u) * 16)

__global__ __launch_bounds__(256)
void flash_mma(const __half* __restrict__ Qg, const __half* __restrict__ Kg,
               const __half* __restrict__ Vtg, __half* __restrict__ Og)
{
    extern __shared__ __align__(16) char fsm[];
    const uint32_t sb = smem_u32(fsm);
    const uint32_t sQ  = sb + QOFFB;
    const uint32_t sK0 = sb + KOFFB;
    const uint32_t sT0 = sb + TOFFB;
    const uint32_t sP  = sb + POFFB;
    __half* Ph = (__half*)(fsm + POFFB);

    const int tid = threadIdx.x;
    const int wid = tid >> 5, lane = tid & 31;
    const int g = lane >> 2, t = lane & 3;
    const int wg = wid >> 2;             // warp group 0/1
    const int gtid = tid & 127;          // thread id within group
    const int qt = (int)(gridDim.x - 1 - blockIdx.x);   // heavy CTAs first
    const int bh = blockIdx.y;
    const int b = bh >> 4, h = bh & 15;
    const int q0 = qt * 256;
    const int ktiles = 4 * qt + 2 + 2 * wg;   // group 0 covers rows < q0+128
    const int mask0  = 4 * qt + 2 * wg;       // first tile needing causal mask
    const size_t base = (size_t)b * Tv * Cv + (size_t)h * Dv;
    const __half* vtb = Vtg + (size_t)bh * Dv * Tv;

    // group buffer bases (double buffer per group)
    const uint32_t sKg = sK0 + wg * 2 * KVTB;
    const uint32_t sTg = sT0 + wg * 2 * KVTB;

    // ---- prologue: all threads load Q; each group loads its tile 0
    {
        const __half* qb = Qg + base + (size_t)q0 * Cv;
        #pragma unroll
        for (int i = 0; i < 8; i++) {
            int id = tid + i * 256, r = id >> 3, u = id & 7;
            cp16(HADDR(sQ, r, u), qb + (size_t)r * Cv + u * 8);
        }
        const __half* kb = Kg + base;
        #pragma unroll
        for (int i = 0; i < 4; i++) {     // 512 units per tile / 128 thr = 4
            int id = gtid + i * 128, r = id >> 3, u = id & 7;
            cp16(HADDR(sKg, r, u), kb + (size_t)r * Cv + u * 8);
            cp16(HADDR(sTg, r, u), vtb + (size_t)r * Tv + u * 8);
        }
        asm volatile("cp.async.commit_group;");
        asm volatile("cp.async.wait_group 0;");
        __syncthreads();                  // Q + both groups' tile 0 visible
    }

    float oacc[2][8][4];
    #pragma unroll
    for (int mf = 0; mf < 2; mf++)
        #pragma unroll
        for (int nf = 0; nf < 8; nf++)
            #pragma unroll
            for (int k = 0; k < 4; k++) oacc[mf][nf][k] = 0.f;
    float mrow[2][2], lrow[2][2];
    #pragma unroll
    for (int mf = 0; mf < 2; mf++) {
        mrow[mf][0] = -1e30f; mrow[mf][1] = -1e30f;
        lrow[mf][0] = 0.f;    lrow[mf][1] = 0.f;
    }

    // Q fragments (log2-domain scale folded into projection)
    uint32_t qf[2][4][4];
    #pragma unroll
    for (int mf = 0; mf < 2; mf++)
        #pragma unroll
        for (int ks = 0; ks < 4; ks++) {
            int row = wid * 32 + mf * 16 + (lane & 15);
            int u = ks * 2 + (lane >> 4);
            LDM_X4(qf[mf][ks][0], qf[mf][ks][1], qf[mf][ks][2], qf[mf][ks][3],
                   HADDR(sQ, row, u));
        }

    for (int kt = 0; kt < ktiles; ++kt) {
        if (kt > 0) {
            asm volatile("cp.async.wait_group 0;");
            GBAR(1 + wg);                 // group-only barrier
        }
        if (kt + 1 < ktiles) {            // prefetch next tile into other buffer
            int nb = (kt + 1) & 1;
            const __half* kb = Kg + base + (size_t)((kt + 1) * 64) * Cv;
            const __half* vb = vtb + (kt + 1) * 64;
            #pragma unroll
            for (int i = 0; i < 4; i++) {
                int id = gtid + i * 128, r = id >> 3, u = id & 7;
                cp16(HADDR(sKg + nb * KVTB, r, u), kb + (size_t)r * Cv + u * 8);
                cp16(HADDR(sTg + nb * KVTB, r, u), vb + (size_t)r * Tv + u * 8);
            }
            asm volatile("cp.async.commit_group;");
        }
        const uint32_t sKb = sKg + (kt & 1) * KVTB;
        const uint32_t sTb = sTg + (kt & 1) * KVTB;

        // ---- S = Q K^T  (log2 domain)
        float sacc[2][8][4];
        #pragma unroll
        for (int mf = 0; mf < 2; mf++)
            #pragma unroll
            for (int nf = 0; nf < 8; nf++)
                #pragma unroll
                for (int k = 0; k < 4; k++) sacc[mf][nf][k] = 0.f;

        #pragma unroll
        for (int ks = 0; ks < 4; ks++) {
            const int u0 = ks * 2;
            uint32_t bf[8][2];
            #pragma unroll
            for (int np = 0; np < 4; np++) {
                int row = np * 16 + ((lane & 16) >> 1) + (lane & 7);
                int u = u0 + ((lane & 8) >> 3);
                uint32_t r0, r1, r2, r3;
                LDM_X4(r0, r1, r2, r3, HADDR(sKb, row, u));
                bf[np*2+0][0] = r0; bf[np*2+0][1] = r1;
                bf[np*2+1][0] = r2; bf[np*2+1][1] = r3;
            }
            #pragma unroll
            for (int mf = 0; mf < 2; mf++)
                #pragma unroll
                for (int nf = 0; nf < 8; nf++)
                    mma_f16(sacc[mf][nf], qf[mf][ks], bf[nf]);
        }

        // ---- causal mask (band tiles of this group)
        if (kt >= mask0) {
            const int k0 = kt * 64;
            #pragma unroll
            for (int mf = 0; mf < 2; mf++) {
                int r0g = q0 + wid * 32 + mf * 16 + g, r1g = r0g + 8;
                #pragma unroll
                for (int nf = 0; nf < 8; nf++) {
                    int c0 = k0 + nf * 8 + 2 * t;
                    if (c0     > r0g) sacc[mf][nf][0] = -1e30f;
                    if (c0 + 1 > r0g) sacc[mf][nf][1] = -1e30f;
                    if (c0     > r1g) sacc[mf][nf][2] = -1e30f;
                    if (c0 + 1 > r1g) sacc[mf][nf][3] = -1e30f;
                }
            }
        }

        // ---- online softmax (log2 domain, h2exp2)
        __half2 pk[2][8][2];
        #pragma unroll
        for (int mf = 0; mf < 2; mf++) {
            float mx0 = -1e30f, mx1 = -1e30f;
            #pragma unroll
            for (int nf = 0; nf < 8; nf++) {
                mx0 = fmaxf(mx0, fmaxf(sacc[mf][nf][0], sacc[mf][nf][1]));
                mx1 = fmaxf(mx1, fmaxf(sacc[mf][nf][2], sacc[mf][nf][3]));
            }
            #pragma unroll
            for (int off = 1; off < 4; off <<= 1) {
                mx0 = fmaxf(mx0, __shfl_xor_sync(0xffffffffu, mx0, off));
                mx1 = fmaxf(mx1, __shfl_xor_sync(0xffffffffu, mx1, off));
            }
            float nm0 = fmaxf(mrow[mf][0], mx0), nm1 = fmaxf(mrow[mf][1], mx1);
            float al0 = exp2f(mrow[mf][0] - nm0), al1 = exp2f(mrow[mf][1] - nm1);
            float rs0 = 0.f, rs1 = 0.f;
            #pragma unroll
            for (int nf = 0; nf < 8; nf++) {
                __half2 p01 = h2exp2(__floats2half2_rn(sacc[mf][nf][0] - nm0,
                                                       sacc[mf][nf][1] - nm0));
                __half2 p23 = h2exp2(__floats2half2_rn(sacc[mf][nf][2] - nm1,
                                                       sacc[mf][nf][3] - nm1));
                pk[mf][nf][0] = p01; pk[mf][nf][1] = p23;
                float2 f01 = __half22float2(p01);
                float2 f23 = __half22float2(p23);
                rs0 += f01.x + f01.y;
                rs1 += f23.x + f23.y;
            }
            #pragma unroll
            for (int off = 1; off < 4; off <<= 1) {
                rs0 += __shfl_xor_sync(0xffffffffu, rs0, off);
                rs1 += __shfl_xor_sync(0xffffffffu, rs1, off);
            }
            lrow[mf][0] = lrow[mf][0] * al0 + rs0; mrow[mf][0] = nm0;
            lrow[mf][1] = lrow[mf][1] * al1 + rs1; mrow[mf][1] = nm1;
            #pragma unroll
            for (int nf = 0; nf < 8; nf++) {
                oacc[mf][nf][0] *= al0; oacc[mf][nf][1] *= al0;
                oacc[mf][nf][2] *= al1; oacc[mf][nf][3] *= al1;
            }
        }

        // ---- P -> warp-private smem rows (fp16x2 packed)
        __syncwarp();
        #pragma unroll
        for (int mf = 0; mf < 2; mf++) {
            int pr0 = wid * 32 + mf * 16 + g, pr1 = pr0 + 8;
            #pragma unroll
            for (int nf = 0; nf < 8; nf++) {
                *(__half2*)&Ph[pr0 * HPAD + nf * 8 + 2 * t] = pk[mf][nf][0];
                *(__half2*)&Ph[pr1 * HPAD + nf * 8 + 2 * t] = pk[mf][nf][1];
            }
        }
        __syncwarp();

        // ---- O += P V
        #pragma unroll
        for (int ks = 0; ks < 4; ks++) {
            const int u0 = ks * 2;
            uint32_t af[2][4];
            #pragma unroll
            for (int mf = 0; mf < 2; mf++) {
                int row = wid * 32 + mf * 16 + (lane & 15);
                int u = u0 + (lane >> 4);
                LDM_X4(af[mf][0], af[mf][1], af[mf][2], af[mf][3], HADDR(sP, row, u));
            }
            uint32_t bf[8][2];
            #pragma unroll
            for (int np = 0; np < 4; np++) {
                int brow = np * 16 + ((lane & 16) >> 1) + (lane & 7);
                int u = u0 + ((lane & 8) >> 3);
                uint32_t r0, r1, r2, r3;
                LDM_X4(r0, r1, r2, r3, HADDR(sTb, brow, u));
                bf[np*2+0][0] = r0; bf[np*2+0][1] = r1;
                bf[np*2+1][0] = r2; bf[np*2+1][1] = r3;
            }
            #pragma unroll
            for (int mf = 0; mf < 2; mf++)
                #pragma unroll
                for (int nf = 0; nf < 8; nf++)
                    mma_f16(oacc[mf][nf], af[mf], bf[nf]);
        }
    }

    // ---- epilogue: normalize, write att as fp16
    #pragma unroll
    for (int mf = 0; mf < 2; mf++) {
        float inv0 = 1.f / lrow[mf][0], inv1 = 1.f / lrow[mf][1];
        int r0g = q0 + wid * 32 + mf * 16 + g, r1g = r0g + 8;
        #pragma unroll
        for (int nf = 0; nf < 8; nf++) {
            int c = nf * 8 + 2 * t;
            *(__half2*)(Og + base + (size_t)r0g * Cv + c) =
                __floats2half2_rn(oacc[mf][nf][0] * inv0, oacc[mf][nf][1] * inv0);
            *(__half2*)(Og + base + (size_t)r1g * Cv + c) =
                __floats2half2_rn(oacc[mf][nf][2] * inv1, oacc[mf][nf][3] * inv1);
        }
    }
}

// ---------------------------------------------------------------------------
extern "C" void kernel_launch(void* const* d_in, const int* in_sizes, int n_in,
                              void* d_out, int out_size)
{
    const float* x  = (const float*)d_in[0];
    const float* wq = (const float*)d_in[1];
    const float* wk = (const float*)d_in[2];
    const float* wv = (const float*)d_in[3];
    const float* wo = (const float*)d_in[4];
    float* out = (float*)d_out;

    __half *qp, *kp, *vtp, *ap, *xh, *wh;
    cudaGetSymbolAddress((void**)&qp, g_q);
    cudaGetSymbolAddress((void**)&kp, g_k);
    cudaGetSymbolAddress((void**)&vtp, g_vt);
    cudaGetSymbolAddress((void**)&ap, g_att);
    cudaGetSymbolAddress((void**)&xh, g_xh);
    cudaGetSymbolAddress((void**)&wh, g_wh);

    const int ntot = (Mv * Cv + 4 * Cv * Cv) / 4;
    round_all<<<(ntot + 255) / 256, 256>>>((const float4*)x,
                                           (const float4*)wq, (const float4*)wk,
                                           (const float4*)wv, (const float4*)wo,
                                           (__half2*)xh, (__half2*)wh);

    const int gsmem = 3 * STGB;   // 98304
    cudaFuncSetAttribute(gemm_h, cudaFuncAttributeMaxDynamicSharedMemorySize, gsmem);

    // fused QKV: Q pre-scaled 0.125*log2e; V written transposed into g_vt
    gemm_h<<<dim3(24, Mv/128), 256, gsmem>>>(xh, wh, qp, kp, vtp, 1);

    cudaFuncSetAttribute(flash_mma, cudaFuncAttributeMaxDynamicSharedMemorySize, FSMEM);
    flash_mma<<<dim3(Tv/256, Bv*Hv), 256, FSMEM>>>(qp, kp, vtp, ap);

    gemm_h<<<dim3(8, Mv/128), 256, gsmem>>>(ap, wh + 3*(size_t)Cv*Cv, out,
                                            nullptr, nullptr, 0);
}